// round 10
// baseline (speedup 1.0000x reference)
#include <cuda_runtime.h>
#include <math.h>

#define C_DIM 128
#define S_DIM 4096
#define HW 176          // 16 * 11
#define HW4 44          // HW / 4
#define B_SEG 32
#define O_DIM 256
#define OSLICE 32       // o per conv-slice block
#define NSLICE 8        // conv slices per b (last NSLICE arrivers)
#define PART_LEN 44     // 4 rows * 11
#define GEM_EPS 1e-6f
#define NEG_INF -3.402823466e38f

// scratch
__device__ float g_pooled[B_SEG * C_DIM * HW];   // [b][c][hw]
__device__ int   g_cnt[B_SEG];

__device__ __forceinline__ float4 max4(float4 a, float4 b) {
    float4 r;
    r.x = fmaxf(a.x, b.x); r.y = fmaxf(a.y, b.y);
    r.z = fmaxf(a.z, b.z); r.w = fmaxf(a.w, b.w);
    return r;
}

__device__ __forceinline__ unsigned long long pack2(float v) {
    unsigned long long r;
    asm("mov.b64 %0, {%1, %1};" : "=l"(r) : "f"(v));
    return r;
}
__device__ __forceinline__ void unpack2(unsigned long long v, float& lo, float& hi) {
    asm("mov.b64 {%0, %1}, %2;" : "=f"(lo), "=f"(hi) : "l"(v));
}
__device__ __forceinline__ void ffma2(unsigned long long& d,
                                      unsigned long long a, unsigned long long b) {
    asm("fma.rn.f32x2 %0, %1, %2, %0;" : "+l"(d) : "l"(a), "l"(b));
}

// GeM power: v^pe. Fast path for pe == 6.5: (v^3)^2 * sqrt(v).
__device__ __forceinline__ float gem_pow(float x, float pe, bool fast65) {
    float v = fmaxf(x, GEM_EPS);
    if (fast65) {
        float v3 = v * v * v;
        return v3 * v3 * sqrtf(v);
    }
    return exp2f(pe * __log2f(v));
}

__global__ void zero_cnt_kernel() {
    if (threadIdx.x < B_SEG) g_cnt[threadIdx.x] = 0;
}

// ---------------------------------------------------------------------------
// Fused kernel. Grid 4096 = (b, c), 352 threads, min 4 blocks/SM
// (reg cap 46 — the seg_max streaming loop fits; conv phase may spill a bit,
// which is fine since only 256/4096 blocks run it).
// Phase 1: ragged segment max for (b, c). Publish via threadfence+atomic.
// Last NSLICE arrivers per b spin for cnt[b]==128 then compute a 32-o
// conv+GeM slice, overlapped with other b's streaming.
// ---------------------------------------------------------------------------
__global__ void __launch_bounds__(352, 4) fused_kernel(
    const float* __restrict__ x, const int* __restrict__ seqL,
    const float* __restrict__ Wmat, const float* __restrict__ p,
    float* __restrict__ out)
{
    __shared__ int sh[3];                         // s0, len, order
    __shared__ float4 smax[8 * HW4];              // 5.6 KB
    __shared__ __align__(16) float ws[C_DIM * OSLICE];   // 16 KB
    __shared__ float ypow[OSLICE * HW];           // 22.5 KB
    __shared__ float pp[4];

    int blk = blockIdx.x;
    int b = blk & (B_SEG - 1);
    int c = blk >> 5;
    int tid = threadIdx.x;

    // ---- Phase 1: segment max ----
    if (tid == 0) {
        int s0 = 0;
        #pragma unroll
        for (int i = 0; i < B_SEG; i++) s0 += (i < b) ? seqL[i] : 0;
        sh[0] = s0;
        sh[1] = seqL[b];
    }
    __syncthreads();

    {
        int sg  = tid / HW4;   // 0..7
        int col = tid % HW4;   // 0..43
        int s0  = sh[0];
        int len = sh[1];

        const float4* bp = reinterpret_cast<const float4*>(x)
                         + (size_t)c * (S_DIM * HW4) + (size_t)s0 * HW4 + col;

        float4 m = make_float4(NEG_INF, NEG_INF, NEG_INF, NEG_INF);
        int s = sg;
        for (; s + 56 < len; s += 64) {
            float4 a0 = __ldcs(&bp[(size_t)(s +  0) * HW4]);
            float4 a1 = __ldcs(&bp[(size_t)(s +  8) * HW4]);
            float4 a2 = __ldcs(&bp[(size_t)(s + 16) * HW4]);
            float4 a3 = __ldcs(&bp[(size_t)(s + 24) * HW4]);
            float4 a4 = __ldcs(&bp[(size_t)(s + 32) * HW4]);
            float4 a5 = __ldcs(&bp[(size_t)(s + 40) * HW4]);
            float4 a6 = __ldcs(&bp[(size_t)(s + 48) * HW4]);
            float4 a7 = __ldcs(&bp[(size_t)(s + 56) * HW4]);
            m = max4(m, max4(max4(max4(a0, a1), max4(a2, a3)),
                             max4(max4(a4, a5), max4(a6, a7))));
        }
        for (; s < len; s += 8) {
            m = max4(m, __ldcs(&bp[(size_t)s * HW4]));
        }

        smax[sg * HW4 + col] = m;
    }
    __syncthreads();

    if (tid < HW4) {
        float4 r = smax[tid];
        #pragma unroll
        for (int g = 1; g < 8; g++) r = max4(r, smax[g * HW4 + tid]);
        reinterpret_cast<float4*>(g_pooled)[(size_t)(b * C_DIM + c) * HW4 + tid] = r;
    }
    __syncthreads();

    // ---- Publish: pooled[b][c] done ----
    if (tid == 0) {
        __threadfence();
        sh[2] = atomicAdd(&g_cnt[b], 1);
    }
    __syncthreads();
    int order = sh[2];
    if (order < C_DIM - NSLICE) return;   // not a conv block

    int o0 = (order - (C_DIM - NSLICE)) * OSLICE;

    // Stage W slice + p while other producers of this b finish
    if (tid < 4) pp[tid] = p[tid];
    for (int i = tid; i < C_DIM * OSLICE; i += 352) {
        int cc = i >> 5;
        int j  = i & (OSLICE - 1);
        ws[i] = Wmat[(o0 + j) * C_DIM + cc];
    }

    // Wait for all 128 producers of this b
    if (tid == 0) {
        while (*(volatile int*)&g_cnt[b] != C_DIM) __nanosleep(100);
        __threadfence();
    }
    __syncthreads();

    // ---- Phase 2: conv slice [32 o] x [176 hw] for batch b ----
    {
        int half = tid / HW;        // 0 or 1 -> o sub-slice of 16
        int hw   = tid % HW;

        unsigned long long acc[8];
        #pragma unroll
        for (int k = 0; k < 8; k++) acc[k] = 0ULL;

        const float* pb  = g_pooled + (size_t)b * C_DIM * HW + hw;
        const float* wsh = ws + half * 16;

        #pragma unroll 4
        for (int cc = 0; cc < C_DIM; cc++) {
            unsigned long long pv2 = pack2(__ldg(&pb[(size_t)cc * HW]));
            const ulonglong2* wr = reinterpret_cast<const ulonglong2*>(
                wsh + cc * OSLICE);
            ulonglong2 w0 = wr[0];
            ulonglong2 w1 = wr[1];
            ulonglong2 w2 = wr[2];
            ulonglong2 w3 = wr[3];
            ffma2(acc[0], pv2, w0.x); ffma2(acc[1], pv2, w0.y);
            ffma2(acc[2], pv2, w1.x); ffma2(acc[3], pv2, w1.y);
            ffma2(acc[4], pv2, w2.x); ffma2(acc[5], pv2, w2.y);
            ffma2(acc[6], pv2, w3.x); ffma2(acc[7], pv2, w3.y);
        }

        int part = hw / PART_LEN;
        float pe = pp[part];
        bool fast65 = (pe == 6.5f);
        int ob = half * 16;
        #pragma unroll
        for (int k = 0; k < 8; k++) {
            float lo, hi;
            unpack2(acc[k], lo, hi);
            ypow[(ob + 2 * k + 0) * HW + hw] = gem_pow(lo, pe, fast65);
            ypow[(ob + 2 * k + 1) * HW + hw] = gem_pow(hi, pe, fast65);
        }
    }
    __syncthreads();

    // 128 threads: one per (o_local, part)
    if (tid < OSLICE * 4) {
        int ol   = tid >> 2;
        int part = tid & 3;
        const float* yp = ypow + ol * HW + part * PART_LEN;
        float sum = 0.0f;
        #pragma unroll
        for (int k = 0; k < PART_LEN; k++) sum += yp[k];
        float pe = pp[part];
        float mean = sum * (1.0f / (float)PART_LEN);
        float g = (mean > 0.0f) ? exp2f(__log2f(mean) / pe) : 0.0f;
        out[((size_t)b * O_DIM + o0 + ol) * 4 + part] = g;
    }
}

extern "C" void kernel_launch(void* const* d_in, const int* in_sizes, int n_in,
                              void* d_out, int out_size)
{
    const float* x    = (const float*)d_in[0];
    const int*   seqL = (const int*)d_in[1];
    const float* Wm   = (const float*)d_in[2];
    const float* p    = (const float*)d_in[3];
    float* out = (float*)d_out;

    zero_cnt_kernel<<<1, 32>>>();
    fused_kernel<<<B_SEG * C_DIM, 352>>>(x, seqL, Wm, p, out);
}

// round 11
// speedup vs baseline: 1.0337x; 1.0337x over previous
#include <cuda_runtime.h>
#include <math.h>

#define C_DIM 128
#define S_DIM 4096
#define HW 176          // 16 * 11
#define HW4 44          // HW / 4
#define B_SEG 32
#define O_DIM 256
#define OSLICE 32       // o per conv-slice block
#define NSLICE 8        // conv slices per b (last NSLICE arrivers)
#define PART_LEN 44     // 4 rows * 11
#define GEM_EPS 1e-6f
#define NEG_INF -3.402823466e38f

// scratch
__device__ float g_pooled[B_SEG * C_DIM * HW];   // [b][c][hw]
__device__ int   g_cnt[B_SEG];

__device__ __forceinline__ float4 max4(float4 a, float4 b) {
    float4 r;
    r.x = fmaxf(a.x, b.x); r.y = fmaxf(a.y, b.y);
    r.z = fmaxf(a.z, b.z); r.w = fmaxf(a.w, b.w);
    return r;
}

__device__ __forceinline__ unsigned long long pack2(float v) {
    unsigned long long r;
    asm("mov.b64 %0, {%1, %1};" : "=l"(r) : "f"(v));
    return r;
}
__device__ __forceinline__ void unpack2(unsigned long long v, float& lo, float& hi) {
    asm("mov.b64 {%0, %1}, %2;" : "=f"(lo), "=f"(hi) : "l"(v));
}
__device__ __forceinline__ void ffma2(unsigned long long& d,
                                      unsigned long long a, unsigned long long b) {
    asm("fma.rn.f32x2 %0, %1, %2, %0;" : "+l"(d) : "l"(a), "l"(b));
}

// GeM power: v^pe. Fast path for pe == 6.5: (v^3)^2 * sqrt(v).
__device__ __forceinline__ float gem_pow(float x, float pe, bool fast65) {
    float v = fmaxf(x, GEM_EPS);
    if (fast65) {
        float v3 = v * v * v;
        return v3 * v3 * sqrtf(v);
    }
    return exp2f(pe * __log2f(v));
}

__global__ void zero_cnt_kernel() {
    if (threadIdx.x < B_SEG) g_cnt[threadIdx.x] = 0;
}

// ---------------------------------------------------------------------------
// Fused kernel. Grid 4096 with B-MAJOR block order: bid = c + 128*b.
// All 128 producers of a b launch contiguously (< one wave), so cnt[b]
// completes early and its 8 conv slices overlap the streaming of later b's.
// Phase 1: ragged segment max for (b, c). Publish via threadfence+atomic.
// Arrival order >= 120 -> compute a 32-o conv+GeM slice for b.
// ---------------------------------------------------------------------------
__global__ void __launch_bounds__(352) fused_kernel(
    const float* __restrict__ x, const int* __restrict__ seqL,
    const float* __restrict__ Wmat, const float* __restrict__ p,
    float* __restrict__ out)
{
    __shared__ int sh[3];                         // s0, len, order
    __shared__ float4 smax[8 * HW4];              // 5.6 KB
    __shared__ __align__(16) float ws[C_DIM * OSLICE];   // 16 KB
    __shared__ float ypow[OSLICE * HW];           // 22.5 KB
    __shared__ float pp[4];

    int blk = blockIdx.x;
    int b = blk >> 7;            // b-major: conv for b becomes ready early
    int c = blk & (C_DIM - 1);
    int tid = threadIdx.x;

    // ---- Phase 1: segment max ----
    if (tid == 0) {
        int s0 = 0;
        #pragma unroll
        for (int i = 0; i < B_SEG; i++) s0 += (i < b) ? seqL[i] : 0;
        sh[0] = s0;
        sh[1] = seqL[b];
    }
    __syncthreads();

    {
        int sg  = tid / HW4;   // 0..7
        int col = tid % HW4;   // 0..43
        int s0  = sh[0];
        int len = sh[1];

        const float4* bp = reinterpret_cast<const float4*>(x)
                         + (size_t)c * (S_DIM * HW4) + (size_t)s0 * HW4 + col;

        float4 m = make_float4(NEG_INF, NEG_INF, NEG_INF, NEG_INF);
        int s = sg;
        for (; s + 56 < len; s += 64) {
            float4 a0 = __ldcs(&bp[(size_t)(s +  0) * HW4]);
            float4 a1 = __ldcs(&bp[(size_t)(s +  8) * HW4]);
            float4 a2 = __ldcs(&bp[(size_t)(s + 16) * HW4]);
            float4 a3 = __ldcs(&bp[(size_t)(s + 24) * HW4]);
            float4 a4 = __ldcs(&bp[(size_t)(s + 32) * HW4]);
            float4 a5 = __ldcs(&bp[(size_t)(s + 40) * HW4]);
            float4 a6 = __ldcs(&bp[(size_t)(s + 48) * HW4]);
            float4 a7 = __ldcs(&bp[(size_t)(s + 56) * HW4]);
            m = max4(m, max4(max4(max4(a0, a1), max4(a2, a3)),
                             max4(max4(a4, a5), max4(a6, a7))));
        }
        for (; s < len; s += 8) {
            m = max4(m, __ldcs(&bp[(size_t)s * HW4]));
        }

        smax[sg * HW4 + col] = m;
    }
    __syncthreads();

    if (tid < HW4) {
        float4 r = smax[tid];
        #pragma unroll
        for (int g = 1; g < 8; g++) r = max4(r, smax[g * HW4 + tid]);
        reinterpret_cast<float4*>(g_pooled)[(size_t)(b * C_DIM + c) * HW4 + tid] = r;
    }
    __syncthreads();

    // ---- Publish: pooled[b][c] done ----
    if (tid == 0) {
        __threadfence();
        sh[2] = atomicAdd(&g_cnt[b], 1);
    }
    __syncthreads();
    int order = sh[2];
    if (order < C_DIM - NSLICE) return;   // not a conv block

    int o0 = (order - (C_DIM - NSLICE)) * OSLICE;

    // Stage W slice + p while the last producers of this b finish
    if (tid < 4) pp[tid] = p[tid];
    for (int i = tid; i < C_DIM * OSLICE; i += 352) {
        int cc = i >> 5;
        int j  = i & (OSLICE - 1);
        ws[i] = Wmat[(o0 + j) * C_DIM + cc];
    }

    // Wait for all 128 producers of this b (short: same len for all c)
    if (tid == 0) {
        while (*(volatile int*)&g_cnt[b] != C_DIM) __nanosleep(64);
        __threadfence();
    }
    __syncthreads();

    // ---- Phase 2: conv slice [32 o] x [176 hw] for batch b ----
    {
        int half = tid / HW;        // 0 or 1 -> o sub-slice of 16
        int hw   = tid % HW;

        unsigned long long acc[8];
        #pragma unroll
        for (int k = 0; k < 8; k++) acc[k] = 0ULL;

        const float* pb  = g_pooled + (size_t)b * C_DIM * HW + hw;
        const float* wsh = ws + half * 16;

        #pragma unroll 4
        for (int cc = 0; cc < C_DIM; cc++) {
            unsigned long long pv2 = pack2(__ldg(&pb[(size_t)cc * HW]));
            const ulonglong2* wr = reinterpret_cast<const ulonglong2*>(
                wsh + cc * OSLICE);
            ulonglong2 w0 = wr[0];
            ulonglong2 w1 = wr[1];
            ulonglong2 w2 = wr[2];
            ulonglong2 w3 = wr[3];
            ffma2(acc[0], pv2, w0.x); ffma2(acc[1], pv2, w0.y);
            ffma2(acc[2], pv2, w1.x); ffma2(acc[3], pv2, w1.y);
            ffma2(acc[4], pv2, w2.x); ffma2(acc[5], pv2, w2.y);
            ffma2(acc[6], pv2, w3.x); ffma2(acc[7], pv2, w3.y);
        }

        int part = hw / PART_LEN;
        float pe = pp[part];
        bool fast65 = (pe == 6.5f);
        int ob = half * 16;
        #pragma unroll
        for (int k = 0; k < 8; k++) {
            float lo, hi;
            unpack2(acc[k], lo, hi);
            ypow[(ob + 2 * k + 0) * HW + hw] = gem_pow(lo, pe, fast65);
            ypow[(ob + 2 * k + 1) * HW + hw] = gem_pow(hi, pe, fast65);
        }
    }
    __syncthreads();

    // 128 threads: one per (o_local, part)
    if (tid < OSLICE * 4) {
        int ol   = tid >> 2;
        int part = tid & 3;
        const float* yp = ypow + ol * HW + part * PART_LEN;
        float sum = 0.0f;
        #pragma unroll
        for (int k = 0; k < PART_LEN; k++) sum += yp[k];
        float pe = pp[part];
        float mean = sum * (1.0f / (float)PART_LEN);
        float g = (mean > 0.0f) ? exp2f(__log2f(mean) / pe) : 0.0f;
        out[((size_t)b * O_DIM + o0 + ol) * 4 + part] = g;
    }
}

extern "C" void kernel_launch(void* const* d_in, const int* in_sizes, int n_in,
                              void* d_out, int out_size)
{
    const float* x    = (const float*)d_in[0];
    const int*   seqL = (const int*)d_in[1];
    const float* Wm   = (const float*)d_in[2];
    const float* p    = (const float*)d_in[3];
    float* out = (float*)d_out;

    zero_cnt_kernel<<<1, 32>>>();
    fused_kernel<<<B_SEG * C_DIM, 352>>>(x, seqL, Wm, p, out);
}